// round 9
// baseline (speedup 1.0000x reference)
#include <cuda_runtime.h>
#include <cstdint>

#define DM 2048
#define DS 16
#define SEQ 4096
#define NB 4
#define NROWS (NB*SEQ)
#define CHL 32                 // chunk body length
#define CHW 20                 // warmup steps (contraction ~0.08^20 ~ 1e-22)
#define NCHUNK (SEQ/CHL)       // 128 chunks per batch

// ---- scratch (static device arrays: no allocation allowed) ----
__device__ float  g_u[NROWS*DS + 1024]; // padded: prefetch overrun safe
__device__ float2 g_murs[NROWS];
__device__ float  g_hist2[NROWS*32];    // stride 32; lanes 16-31 write junk cols

__device__ __forceinline__ float tanh_fast(float x){
    float y;
    asm("tanh.approx.f32 %0, %1;" : "=f"(y) : "f"(x));
    return y;
}

// ---------------------------------------------------------------------------
// kernA: LN stats + u projection. TWO rows per iteration, ONE barrier per
//   iteration; row B's dots overlap row A's shuffle-chain latency. Warp 0
//   does both rows' serial tails while warps 1-7 run ahead (double-buffered
//   partials over iterations).
// ---------------------------------------------------------------------------
__global__ __launch_bounds__(256, 1)
void kernA(const float* __restrict__ x,
           const float* __restrict__ B,
           const float* __restrict__ gamma,
           const float* __restrict__ beta){
    const int tid  = threadIdx.x;
    const int lane = tid & 31, warp = tid >> 5;
    const int d0   = tid * 8;
    const unsigned FULL = 0xFFFFFFFFu;

    __shared__ float spart[2][2][64][20]; // [iterbuf][rowInPair][slot][value]
    __shared__ float scb[32];             // cB[16], bB[16]

    float gg[8], bt[8];
    {
        float4 t0 = *(const float4*)(gamma + d0);
        float4 t1 = *(const float4*)(gamma + d0 + 4);
        gg[0]=t0.x; gg[1]=t0.y; gg[2]=t0.z; gg[3]=t0.w;
        gg[4]=t1.x; gg[5]=t1.y; gg[6]=t1.z; gg[7]=t1.w;
        float4 u0 = *(const float4*)(beta + d0);
        float4 u1 = *(const float4*)(beta + d0 + 4);
        bt[0]=u0.x; bt[1]=u0.y; bt[2]=u0.z; bt[3]=u0.w;
        bt[4]=u1.x; bt[5]=u1.y; bt[6]=u1.z; bt[7]=u1.w;
    }

    float bg[16][8];                   // gamma-folded B, register-resident
    {
        float pc[16], pb[16];
        #pragma unroll
        for (int s = 0; s < 16; s++){
            float4 b0 = *(const float4*)(B + s*DM + d0);
            float4 b1 = *(const float4*)(B + s*DM + d0 + 4);
            float br[8] = {b0.x,b0.y,b0.z,b0.w,b1.x,b1.y,b1.z,b1.w};
            float c = 0.f, b2 = 0.f;
            #pragma unroll
            for (int k = 0; k < 8; k++){
                bg[s][k] = br[k] * gg[k];
                c  += bg[s][k];
                b2  = fmaf(bt[k], br[k], b2);
            }
            pc[s] = c; pb[s] = b2;
        }
        #pragma unroll
        for (int off = 16; off > 0; off >>= 1){
            #pragma unroll
            for (int s = 0; s < 16; s++){
                pc[s] += __shfl_xor_sync(FULL, pc[s], off);
                pb[s] += __shfl_xor_sync(FULL, pb[s], off);
            }
        }
        if (lane == 0){
            #pragma unroll
            for (int s = 0; s < 16; s++){
                spart[0][0][warp][s]     = pc[s];
                spart[0][0][8 + warp][s] = pb[s];
            }
        }
        __syncthreads();
        if (tid < 32){
            int i = tid & 15, grp = tid >> 4;
            float t = spart[0][0][grp*8 + 0][i];
            #pragma unroll
            for (int w = 1; w < 8; w++) t += spart[0][0][grp*8 + w][i];
            scb[tid] = t;
        }
        __syncthreads();
    }
    float cBl = scb[lane & 15];
    float bBl = scb[16 + (lane & 15)];
    __syncthreads();

    int row = blockIdx.x;
    const int stride = gridDim.x;
    const int step   = 2*stride;
    int pb2 = 0;

    auto ldx4 = [&](int r, int off){
        int rc = r < NROWS ? r : 0;
        return *(const float4*)(x + (size_t)rc*DM + d0 + off);
    };
    float4 Ax0 = ldx4(row, 0),          Ax1 = ldx4(row, 4);
    float4 Bx0 = ldx4(row+stride, 0),   Bx1 = ldx4(row+stride, 4);
    float4 Ap0 = ldx4(row+step, 0),     Ap1 = ldx4(row+step, 4);
    float4 Bp0 = ldx4(row+step+stride,0), Bp1 = ldx4(row+step+stride,4);

    for (; row < NROWS; row += step){
        const int rB = row + stride;
        float xsA[8] = {Ax0.x,Ax0.y,Ax0.z,Ax0.w, Ax1.x,Ax1.y,Ax1.z,Ax1.w};
        float xsB[8] = {Bx0.x,Bx0.y,Bx0.z,Bx0.w, Bx1.x,Bx1.y,Bx1.z,Bx1.w};
        Ax0 = Ap0; Ax1 = Ap1; Bx0 = Bp0; Bx1 = Bp1;
        {
            int nr = row + 2*step;
            Ap0 = ldx4(nr, 0);          Ap1 = ldx4(nr, 4);
            Bp0 = ldx4(nr+stride, 0);   Bp1 = ldx4(nr+stride, 4);
        }

        // ---- row A ----
        float pA[18];
        {
            float s1 = 0.f, s2 = 0.f;
            #pragma unroll
            for (int k = 0; k < 8; k++){ s1 += xsA[k]; s2 = fmaf(xsA[k], xsA[k], s2); }
            pA[16] = s1; pA[17] = s2;
        }
        #pragma unroll
        for (int s = 0; s < 16; s++){
            float acc = xsA[0]*bg[s][0];
            #pragma unroll
            for (int k = 1; k < 8; k++) acc = fmaf(xsA[k], bg[s][k], acc);
            pA[s] = acc;
        }
        #pragma unroll
        for (int i = 0; i < 18; i++) pA[i] += __shfl_xor_sync(FULL, pA[i], 16);
        #pragma unroll
        for (int i = 0; i < 18; i++) pA[i] += __shfl_xor_sync(FULL, pA[i], 8);
        if (lane < 8){
            float* dst = spart[pb2][0][warp*8 + lane];
            *(float4*)(dst)      = make_float4(pA[0],  pA[1],  pA[2],  pA[3]);
            *(float4*)(dst + 4)  = make_float4(pA[4],  pA[5],  pA[6],  pA[7]);
            *(float4*)(dst + 8)  = make_float4(pA[8],  pA[9],  pA[10], pA[11]);
            *(float4*)(dst + 12) = make_float4(pA[12], pA[13], pA[14], pA[15]);
            *(float2*)(dst + 16) = make_float2(pA[16], pA[17]);
        }

        // ---- row B (dots independent of A's shuffles -> overlap) ----
        float pB[18];
        {
            float s1 = 0.f, s2 = 0.f;
            #pragma unroll
            for (int k = 0; k < 8; k++){ s1 += xsB[k]; s2 = fmaf(xsB[k], xsB[k], s2); }
            pB[16] = s1; pB[17] = s2;
        }
        #pragma unroll
        for (int s = 0; s < 16; s++){
            float acc = xsB[0]*bg[s][0];
            #pragma unroll
            for (int k = 1; k < 8; k++) acc = fmaf(xsB[k], bg[s][k], acc);
            pB[s] = acc;
        }
        #pragma unroll
        for (int i = 0; i < 18; i++) pB[i] += __shfl_xor_sync(FULL, pB[i], 16);
        #pragma unroll
        for (int i = 0; i < 18; i++) pB[i] += __shfl_xor_sync(FULL, pB[i], 8);
        if (lane < 8){
            float* dst = spart[pb2][1][warp*8 + lane];
            *(float4*)(dst)      = make_float4(pB[0],  pB[1],  pB[2],  pB[3]);
            *(float4*)(dst + 4)  = make_float4(pB[4],  pB[5],  pB[6],  pB[7]);
            *(float4*)(dst + 8)  = make_float4(pB[8],  pB[9],  pB[10], pB[11]);
            *(float4*)(dst + 12) = make_float4(pB[12], pB[13], pB[14], pB[15]);
            *(float2*)(dst + 16) = make_float2(pB[16], pB[17]);
        }

        __syncthreads();               // ONE barrier per 2 rows
        if (warp == 0){                // warp 0 tails both rows; others run ahead
            float a0=0.f,a1=0.f,a2=0.f,a3=0.f, b0=0.f,b1=0.f,b2=0.f,b3=0.f;
            #pragma unroll
            for (int j = 0; j < 64; j += 4){
                a0 += spart[pb2][0][j    ][lane];
                a1 += spart[pb2][0][j + 1][lane];
                a2 += spart[pb2][0][j + 2][lane];
                a3 += spart[pb2][0][j + 3][lane];
                b0 += spart[pb2][1][j    ][lane];
                b1 += spart[pb2][1][j + 1][lane];
                b2 += spart[pb2][1][j + 2][lane];
                b3 += spart[pb2][1][j + 3][lane];
            }
            float tA = (a0 + a1) + (a2 + a3);
            float tB = (b0 + b1) + (b2 + b3);
            float sA1 = __shfl_sync(FULL, tA, 16);
            float sA2 = __shfl_sync(FULL, tA, 17);
            float sB1 = __shfl_sync(FULL, tB, 16);
            float sB2 = __shfl_sync(FULL, tB, 17);
            float muA  = sA1 * (1.0f/DM);
            float varA = sA2 * (1.0f/DM) - muA*muA;
            float rsA  = rsqrtf(varA + 1e-5f);
            float muB  = sB1 * (1.0f/DM);
            float varB = sB2 * (1.0f/DM) - muB*muB;
            float rsB  = rsqrtf(varB + 1e-5f);
            if (lane < 16){
                g_u[row*DS + lane] = fmaf(-muA, cBl, tA) * rsA + bBl;
            } else if (lane == 16){
                g_murs[row] = make_float2(muA, rsA);
            }
            if (rB < NROWS){
                if (lane < 16){
                    g_u[rB*DS + lane] = fmaf(-muB, cBl, tB) * rsB + bBl;
                } else if (lane == 16){
                    g_murs[rB] = make_float2(muB, rsB);
                }
            }
        }
        pb2 ^= 1;
    }
}

// ---------------------------------------------------------------------------
// kernScan: chunked-parallel exact scan (unchanged).
// ---------------------------------------------------------------------------
__global__ __launch_bounds__(32, 1)
void kernScan(const float* __restrict__ A){
    const int chunk = blockIdx.x;
    const int b     = chunk / NCHUNK;
    const int c     = chunk % NCHUNK;
    const int t0    = c * CHL;
    const int start = (c == 0) ? 0 : (t0 - CHW);
    const int steps = t0 + CHL - start;
    const int lane  = threadIdx.x;

    float a[16];
    #pragma unroll
    for (int j = 0; j < 16; j++) a[j] = A[j*DS + (lane & 15)];

    const float* ub = g_u     + (size_t)b * SEQ * DS + (size_t)start * DS;
    float*       hb = g_hist2 + (size_t)(b * SEQ + start) * 32;

    __shared__ float sh[2][32];
    sh[0][lane] = 0.f;
    __syncthreads();

    float uq[4];
    #pragma unroll
    for (int k = 0; k < 4; k++) uq[k] = ub[k*DS + lane];

    const int body0 = t0 - start;
    for (int s = 0; s < steps; s += 4){
        #pragma unroll
        for (int k = 0; k < 4; k++){
            const int i = s + k;
            const int p = i & 1;
            float uc = uq[k];
            uq[k] = ub[(i + 4)*DS + lane];

            float4 H0 = *(const float4*)&sh[p][0];
            float4 H1 = *(const float4*)&sh[p][4];
            float4 H2 = *(const float4*)&sh[p][8];
            float4 H3 = *(const float4*)&sh[p][12];

            float a0 = fmaf(H0.x, a[0], uc);
            float a1 = H0.y * a[1];
            float a2 = H0.z * a[2];
            float a3 = H0.w * a[3];
            float a4 = H1.x * a[4];
            float a5 = H1.y * a[5];
            float a6 = H1.z * a[6];
            float a7 = H1.w * a[7];
            a0 = fmaf(H2.x, a[8],  a0);
            a1 = fmaf(H2.y, a[9],  a1);
            a2 = fmaf(H2.z, a[10], a2);
            a3 = fmaf(H2.w, a[11], a3);
            a4 = fmaf(H3.x, a[12], a4);
            a5 = fmaf(H3.y, a[13], a5);
            a6 = fmaf(H3.z, a[14], a6);
            a7 = fmaf(H3.w, a[15], a7);
            float v = ((a0 + a1) + (a2 + a3)) + ((a4 + a5) + (a6 + a7));
            float h = tanh_fast(v);

            sh[p ^ 1][lane] = h;
            __syncthreads();

            if (i >= body0) hb[i*32 + lane] = h;
        }
    }
}

// ---------------------------------------------------------------------------
// kernC: out = h@C + (1+Dp)*(gamma*(x-mu)*rs + beta).  Half-DM split,
//   pairwise rows; x, murs AND hist all prefetched one pair-iteration ahead
//   (the uniform L2-far murs/hist loads were the serializer).
// ---------------------------------------------------------------------------
__global__ __launch_bounds__(256, 1)
void kernC(const float* __restrict__ x,
           const float* __restrict__ Cm,
           const float* __restrict__ Dp,
           const float* __restrict__ gamma,
           const float* __restrict__ beta,
           float* __restrict__ out){
    const int tid  = threadIdx.x;
    const int half = blockIdx.x & 1;
    const int d0   = half * (DM/2) + tid * 4;

    float e[4], f[4];
    {
        float4 dp = *(const float4*)(Dp    + d0);
        float4 g  = *(const float4*)(gamma + d0);
        float4 btv= *(const float4*)(beta  + d0);
        float dv[4] = {dp.x,dp.y,dp.z,dp.w};
        float gv[4] = {g.x,g.y,g.z,g.w};
        float bv[4] = {btv.x,btv.y,btv.z,btv.w};
        #pragma unroll
        for (int k = 0; k < 4; k++){
            float cc = 1.0f + dv[k];
            e[k] = cc * gv[k];
            f[k] = cc * bv[k];
        }
    }
    float cr[16][4];
    #pragma unroll
    for (int s = 0; s < 16; s++){
        float4 c0 = *(const float4*)(Cm + s*DM + d0);
        cr[s][0]=c0.x; cr[s][1]=c0.y; cr[s][2]=c0.z; cr[s][3]=c0.w;
    }

    const int base = blockIdx.x >> 1;             // 0..147
    auto rcl = [&](int r){ return r < NROWS ? r : NROWS-1; };
    auto ldx = [&](int r){
        return *(const float4*)(x + (size_t)rcl(r)*DM + d0);
    };

    // current pair state
    float4 xA = ldx(base),        xB = ldx(base + 148);
    float2 mA = g_murs[base],     mB = g_murs[rcl(base + 148)];
    const float4* hpA = (const float4*)(g_hist2 + (size_t)base*32);
    const float4* hpB = (const float4*)(g_hist2 + (size_t)rcl(base+148)*32);
    float4 hA0 = hpA[0], hA1 = hpA[1], hA2 = hpA[2], hA3 = hpA[3];
    float4 hB0 = hpB[0], hB1 = hpB[1], hB2 = hpB[2], hB3 = hpB[3];

    // next pair state (prefetched)
    float4 nxA = ldx(base + 296), nxB = ldx(base + 444);
    float2 nmA = g_murs[rcl(base + 296)], nmB = g_murs[rcl(base + 444)];
    const float4* nhpA = (const float4*)(g_hist2 + (size_t)rcl(base+296)*32);
    const float4* nhpB = (const float4*)(g_hist2 + (size_t)rcl(base+444)*32);
    float4 nhA0 = nhpA[0], nhA1 = nhpA[1], nhA2 = nhpA[2], nhA3 = nhpA[3];
    float4 nhB0 = nhpB[0], nhB1 = nhpB[1], nhB2 = nhpB[2], nhB3 = nhpB[3];

    for (int r = base; r < NROWS; r += 296){
        // snapshot current
        float xsA[4] = {xA.x, xA.y, xA.z, xA.w};
        float xsB[4] = {xB.x, xB.y, xB.z, xB.w};
        float2 mrA = mA, mrB = mB;
        float hvA[16] = {hA0.x,hA0.y,hA0.z,hA0.w, hA1.x,hA1.y,hA1.z,hA1.w,
                         hA2.x,hA2.y,hA2.z,hA2.w, hA3.x,hA3.y,hA3.z,hA3.w};
        float hvB[16] = {hB0.x,hB0.y,hB0.z,hB0.w, hB1.x,hB1.y,hB1.z,hB1.w,
                         hB2.x,hB2.y,hB2.z,hB2.w, hB3.x,hB3.y,hB3.z,hB3.w};

        // rotate next -> current, issue prefetch for r+592 pair
        xA = nxA; xB = nxB; mA = nmA; mB = nmB;
        hA0 = nhA0; hA1 = nhA1; hA2 = nhA2; hA3 = nhA3;
        hB0 = nhB0; hB1 = nhB1; hB2 = nhB2; hB3 = nhB3;
        {
            int ra = r + 592, rb = r + 740;
            nxA = ldx(ra); nxB = ldx(rb);
            nmA = g_murs[rcl(ra)]; nmB = g_murs[rcl(rb)];
            const float4* pa = (const float4*)(g_hist2 + (size_t)rcl(ra)*32);
            const float4* pb = (const float4*)(g_hist2 + (size_t)rcl(rb)*32);
            nhA0 = pa[0]; nhA1 = pa[1]; nhA2 = pa[2]; nhA3 = pa[3];
            nhB0 = pb[0]; nhB1 = pb[1]; nhB2 = pb[2]; nhB3 = pb[3];
        }

        int rB = r + 148;
        float oA[4], oB[4];
        #pragma unroll
        for (int k = 0; k < 4; k++){
            float xcA = (xsA[k] - mrA.x) * mrA.y;
            float xcB = (xsB[k] - mrB.x) * mrB.y;
            float aA  = fmaf(e[k], xcA, f[k]);
            float aB  = fmaf(e[k], xcB, f[k]);
            #pragma unroll
            for (int s = 0; s < 16; s++){
                aA = fmaf(hvA[s], cr[s][k], aA);
                aB = fmaf(hvB[s], cr[s][k], aB);
            }
            oA[k] = aA; oB[k] = aB;
        }
        *(float4*)(out + (size_t)r*DM + d0) = make_float4(oA[0], oA[1], oA[2], oA[3]);
        if (rB < NROWS)
            *(float4*)(out + (size_t)rB*DM + d0) = make_float4(oB[0], oB[1], oB[2], oB[3]);
    }
}

// ---------------------------------------------------------------------------
extern "C" void kernel_launch(void* const* d_in, const int* in_sizes, int n_in,
                              void* d_out, int out_size){
    const float* x     = (const float*)d_in[0];
    const float* A     = (const float*)d_in[1];
    const float* B     = (const float*)d_in[2];
    const float* C     = (const float*)d_in[3];
    const float* Dp    = (const float*)d_in[4];
    const float* gamma = (const float*)d_in[5];
    const float* beta  = (const float*)d_in[6];
    float* out = (float*)d_out;

    kernA<<<148, 256>>>(x, B, gamma, beta);
    kernScan<<<NB*NCHUNK, 32>>>(A);
    kernC<<<296, 256>>>(x, C, Dp, gamma, beta, out);
}